// round 1
// baseline (speedup 1.0000x reference)
#include <cuda_runtime.h>

#define THREADS 256
#define WARPS   8
#define PPW     4           // points per warp
#define PPB     (WARPS*PPW) // 32 points per block
#define KC      32          // weight rows staged per chunk
#define HID     256

// ---------------------------------------------------------------------------
// Equation-point kernel: propagates (value, du/dx, d2u/dx2) in forward mode.
// One warp owns PPW points; lane owns output slots j = lane + 32*r, r=0..7.
// h-state lives in shared (warp-private regions), weights staged in chunks.
// ---------------------------------------------------------------------------
__global__ void __launch_bounds__(THREADS, 1)
pinn_d2_kernel(const float* __restrict__ x,
               const float* __restrict__ W0, const float* __restrict__ b0,
               const float* __restrict__ W1, const float* __restrict__ b1,
               const float* __restrict__ W2, const float* __restrict__ b2,
               const float* __restrict__ W3, const float* __restrict__ b3,
               const float* __restrict__ W4,
               float* __restrict__ out)
{
    extern __shared__ float sm[];
    float* hv  = sm;                   // [PPB][HID] value
    float* hd1 = hv  + PPB * HID;      // [PPB][HID] 1st deriv
    float* hd2 = hd1 + PPB * HID;      // [PPB][HID] 2nd deriv
    float* Wc  = hd2 + PPB * HID;      // [KC][HID]  weight chunk

    const int tid   = threadIdx.x;
    const int warp  = tid >> 5;
    const int lane  = tid & 31;
    const int p0    = blockIdx.x * PPB + warp * PPW;  // global point base
    const int wslot = warp * PPW;                     // shared slot base

    // ---- layer 0: scalar input ----
    float xs[PPW];
#pragma unroll
    for (int p = 0; p < PPW; ++p) xs[p] = x[p0 + p];

#pragma unroll
    for (int r = 0; r < 8; ++r) {
        const int j = lane + 32 * r;
        const float w  = W0[j];
        const float bb = b0[j];
#pragma unroll
        for (int p = 0; p < PPW; ++p) {
            const float zv = fmaf(xs[p], w, bb);
            const float a  = tanhf(zv);
            const float s  = 1.0f - a * a;
            hv [(wslot + p) * HID + j] = a;
            hd1[(wslot + p) * HID + j] = s * w;                 // z'=w, z''=0
            hd2[(wslot + p) * HID + j] = s * (-2.0f * a * w * w);
        }
    }

    const float* Wls[3] = {W1, W2, W3};
    const float* bls[3] = {b1, b2, b3};

    for (int l = 0; l < 3; ++l) {
        const float* __restrict__ Wl = Wls[l];
        const float* __restrict__ bl = bls[l];

        float accv[PPW][8], acc1[PPW][8], acc2[PPW][8];
#pragma unroll
        for (int r = 0; r < 8; ++r) {
            const float bb = bl[lane + 32 * r];
#pragma unroll
            for (int p = 0; p < PPW; ++p) {
                accv[p][r] = bb; acc1[p][r] = 0.0f; acc2[p][r] = 0.0f;
            }
        }

        for (int c = 0; c < HID / KC; ++c) {
            __syncthreads();
            // stage KC rows of Wl (coalesced float4)
            const float4* __restrict__ src =
                reinterpret_cast<const float4*>(Wl + c * KC * HID);
            float4* dst = reinterpret_cast<float4*>(Wc);
#pragma unroll
            for (int i = 0; i < (KC * HID / 4) / THREADS; ++i)
                dst[tid + i * THREADS] = src[tid + i * THREADS];
            __syncthreads();

#pragma unroll 2
            for (int kk = 0; kk < KC; ++kk) {
                const int k = c * KC + kk;
                float w[8];
#pragma unroll
                for (int r = 0; r < 8; ++r) w[r] = Wc[kk * HID + lane + 32 * r];
#pragma unroll
                for (int p = 0; p < PPW; ++p) {
                    const float av = hv [(wslot + p) * HID + k];
                    const float a1 = hd1[(wslot + p) * HID + k];
                    const float a2 = hd2[(wslot + p) * HID + k];
#pragma unroll
                    for (int r = 0; r < 8; ++r) {
                        accv[p][r] = fmaf(av, w[r], accv[p][r]);
                        acc1[p][r] = fmaf(a1, w[r], acc1[p][r]);
                        acc2[p][r] = fmaf(a2, w[r], acc2[p][r]);
                    }
                }
            }
        }

        // tanh combine, write next-layer state (warp-private, no sync needed)
#pragma unroll
        for (int r = 0; r < 8; ++r) {
            const int j = lane + 32 * r;
#pragma unroll
            for (int p = 0; p < PPW; ++p) {
                const float a  = tanhf(accv[p][r]);
                const float s  = 1.0f - a * a;
                const float z1 = acc1[p][r];
                hv [(wslot + p) * HID + j] = a;
                hd1[(wslot + p) * HID + j] = s * z1;
                hd2[(wslot + p) * HID + j] = s * (acc2[p][r] - 2.0f * a * z1 * z1);
            }
        }
    }

    // ---- final linear layer: d2u/dx2 = h'' @ W4 (bias drops out) ----
#pragma unroll
    for (int p = 0; p < PPW; ++p) {
        float part = 0.0f;
#pragma unroll
        for (int r = 0; r < 8; ++r) {
            const int j = lane + 32 * r;
            part = fmaf(hd2[(wslot + p) * HID + j], W4[j], part);
        }
#pragma unroll
        for (int o = 16; o > 0; o >>= 1)
            part += __shfl_xor_sync(0xffffffffu, part, o);
        if (lane == 0) out[p0 + p] = part;
    }
}

// ---------------------------------------------------------------------------
// Boundary-point kernel: value stream only.
// ---------------------------------------------------------------------------
__global__ void __launch_bounds__(THREADS, 2)
pinn_u_kernel(const float* __restrict__ x,
              const float* __restrict__ W0, const float* __restrict__ b0,
              const float* __restrict__ W1, const float* __restrict__ b1,
              const float* __restrict__ W2, const float* __restrict__ b2,
              const float* __restrict__ W3, const float* __restrict__ b3,
              const float* __restrict__ W4, const float* __restrict__ b4,
              float* __restrict__ out)
{
    extern __shared__ float sm[];
    float* hv = sm;                 // [PPB][HID]
    float* Wc = hv + PPB * HID;     // [KC][HID]

    const int tid   = threadIdx.x;
    const int warp  = tid >> 5;
    const int lane  = tid & 31;
    const int p0    = blockIdx.x * PPB + warp * PPW;
    const int wslot = warp * PPW;

    float xs[PPW];
#pragma unroll
    for (int p = 0; p < PPW; ++p) xs[p] = x[p0 + p];

#pragma unroll
    for (int r = 0; r < 8; ++r) {
        const int j = lane + 32 * r;
        const float w  = W0[j];
        const float bb = b0[j];
#pragma unroll
        for (int p = 0; p < PPW; ++p)
            hv[(wslot + p) * HID + j] = tanhf(fmaf(xs[p], w, bb));
    }

    const float* Wls[3] = {W1, W2, W3};
    const float* bls[3] = {b1, b2, b3};

    for (int l = 0; l < 3; ++l) {
        const float* __restrict__ Wl = Wls[l];
        const float* __restrict__ bl = bls[l];

        float accv[PPW][8];
#pragma unroll
        for (int r = 0; r < 8; ++r) {
            const float bb = bl[lane + 32 * r];
#pragma unroll
            for (int p = 0; p < PPW; ++p) accv[p][r] = bb;
        }

        for (int c = 0; c < HID / KC; ++c) {
            __syncthreads();
            const float4* __restrict__ src =
                reinterpret_cast<const float4*>(Wl + c * KC * HID);
            float4* dst = reinterpret_cast<float4*>(Wc);
#pragma unroll
            for (int i = 0; i < (KC * HID / 4) / THREADS; ++i)
                dst[tid + i * THREADS] = src[tid + i * THREADS];
            __syncthreads();

#pragma unroll 2
            for (int kk = 0; kk < KC; ++kk) {
                const int k = c * KC + kk;
                float w[8];
#pragma unroll
                for (int r = 0; r < 8; ++r) w[r] = Wc[kk * HID + lane + 32 * r];
#pragma unroll
                for (int p = 0; p < PPW; ++p) {
                    const float av = hv[(wslot + p) * HID + k];
#pragma unroll
                    for (int r = 0; r < 8; ++r)
                        accv[p][r] = fmaf(av, w[r], accv[p][r]);
                }
            }
        }

#pragma unroll
        for (int r = 0; r < 8; ++r) {
            const int j = lane + 32 * r;
#pragma unroll
            for (int p = 0; p < PPW; ++p)
                hv[(wslot + p) * HID + j] = tanhf(accv[p][r]);
        }
    }

    const float b4v = b4[0];
#pragma unroll
    for (int p = 0; p < PPW; ++p) {
        float part = 0.0f;
#pragma unroll
        for (int r = 0; r < 8; ++r) {
            const int j = lane + 32 * r;
            part = fmaf(hv[(wslot + p) * HID + j], W4[j], part);
        }
#pragma unroll
        for (int o = 16; o > 0; o >>= 1)
            part += __shfl_xor_sync(0xffffffffu, part, o);
        if (lane == 0) out[p0 + p] = part + b4v;
    }
}

// ---------------------------------------------------------------------------
extern "C" void kernel_launch(void* const* d_in, const int* in_sizes, int n_in,
                              void* d_out, int out_size)
{
    const float* x_eq = (const float*)d_in[0];   // [262144]
    const float* x_b  = (const float*)d_in[1];   // [8192]
    const float* W0   = (const float*)d_in[2];
    const float* b0   = (const float*)d_in[3];
    const float* W1   = (const float*)d_in[4];
    const float* b1   = (const float*)d_in[5];
    const float* W2   = (const float*)d_in[6];
    const float* b2   = (const float*)d_in[7];
    const float* W3   = (const float*)d_in[8];
    const float* b3   = (const float*)d_in[9];
    const float* W4   = (const float*)d_in[10];
    const float* b4   = (const float*)d_in[11];
    float* out = (float*)d_out;

    const int n_eq = in_sizes[0];   // 262144
    const int n_b  = in_sizes[1];   // 8192

    const size_t smem_d2 = (size_t)(3 * PPB * HID + KC * HID) * sizeof(float); // 128 KB
    const size_t smem_u  = (size_t)(PPB * HID + KC * HID) * sizeof(float);     // 64 KB

    cudaFuncSetAttribute(pinn_d2_kernel,
                         cudaFuncAttributeMaxDynamicSharedMemorySize, (int)smem_d2);
    cudaFuncSetAttribute(pinn_u_kernel,
                         cudaFuncAttributeMaxDynamicSharedMemorySize, (int)smem_u);

    pinn_d2_kernel<<<n_eq / PPB, THREADS, smem_d2>>>(
        x_eq, W0, b0, W1, b1, W2, b2, W3, b3, W4, out);

    pinn_u_kernel<<<n_b / PPB, THREADS, smem_u>>>(
        x_b, W0, b0, W1, b1, W2, b2, W3, b3, W4, b4, out + n_eq);
}

// round 2
// speedup vs baseline: 1.0980x; 1.0980x over previous
#include <cuda_runtime.h>

#define THREADS 256
#define WARPS   8
#define PPW     4             // points per warp
#define NPAIR   (PPW/2)       // point-pairs per warp
#define PPB     (WARPS*PPW)   // 32 points per block
#define KC      32            // weight rows staged per chunk
#define HID     256

typedef unsigned long long u64;

// ---- packed fp32x2 helpers (Blackwell FFMA2; full fp32 precision) ----
__device__ __forceinline__ u64 pk2(float lo, float hi) {
    u64 r; asm("mov.b64 %0, {%1, %2};" : "=l"(r) : "f"(lo), "f"(hi)); return r;
}
__device__ __forceinline__ void upk2(u64 v, float& lo, float& hi) {
    asm("mov.b64 {%0, %1}, %2;" : "=f"(lo), "=f"(hi) : "l"(v));
}
__device__ __forceinline__ void fma2(u64& d, u64 a, u64 b) {
    asm("fma.rn.f32x2 %0, %1, %2, %0;" : "+l"(d) : "l"(a), "l"(b));
}

// ---------------------------------------------------------------------------
// Equation-point kernel: forward-mode (value, u', u'') with packed f32x2 math.
// Warp owns 4 points = 2 pairs; pair state is u64-interleaved in shared so a
// single LDS.64 broadcast feeds both halves of each FFMA2.
// ---------------------------------------------------------------------------
__global__ void __launch_bounds__(THREADS, 1)
pinn_d2_kernel(const float* __restrict__ x,
               const float* __restrict__ W0, const float* __restrict__ b0,
               const float* __restrict__ W1, const float* __restrict__ b1,
               const float* __restrict__ W2, const float* __restrict__ b2,
               const float* __restrict__ W3, const float* __restrict__ b3,
               const float* __restrict__ W4,
               float* __restrict__ out)
{
    extern __shared__ float sm[];
    u64* hv2  = reinterpret_cast<u64*>(sm);             // [PPB/2][HID] value pairs
    u64* hd12 = hv2  + (PPB/2) * HID;                   // [PPB/2][HID] u' pairs
    u64* hd22 = hd12 + (PPB/2) * HID;                   // [PPB/2][HID] u'' pairs
    float* Wc = reinterpret_cast<float*>(hd22 + (PPB/2) * HID);  // [KC][HID]

    const int tid  = threadIdx.x;
    const int warp = tid >> 5;
    const int lane = tid & 31;
    const int p0   = blockIdx.x * PPB + warp * PPW;     // global point base
    const int ps   = warp * NPAIR;                      // pair-slot base

    // ---- layer 0: scalar input ----
    float xs[PPW];
#pragma unroll
    for (int p = 0; p < PPW; ++p) xs[p] = x[p0 + p];

#pragma unroll
    for (int r = 0; r < 8; ++r) {
        const int j = lane + 32 * r;
        const float w  = W0[j];
        const float bb = b0[j];
#pragma unroll
        for (int q = 0; q < NPAIR; ++q) {
            float a[2], d1[2], d2v[2];
#pragma unroll
            for (int h = 0; h < 2; ++h) {
                const float zv = fmaf(xs[2*q + h], w, bb);
                const float av = tanhf(zv);
                const float s  = 1.0f - av * av;
                a[h]   = av;
                d1[h]  = s * w;
                d2v[h] = s * (-2.0f * av * w * w);
            }
            hv2 [(ps + q) * HID + j] = pk2(a[0],   a[1]);
            hd12[(ps + q) * HID + j] = pk2(d1[0],  d1[1]);
            hd22[(ps + q) * HID + j] = pk2(d2v[0], d2v[1]);
        }
    }

    const float* Wls[3] = {W1, W2, W3};
    const float* bls[3] = {b1, b2, b3};

    for (int l = 0; l < 3; ++l) {
        const float* __restrict__ Wl = Wls[l];
        const float* __restrict__ bl = bls[l];

        u64 accv[NPAIR][8], acc1[NPAIR][8], acc2[NPAIR][8];
#pragma unroll
        for (int r = 0; r < 8; ++r) {
            const float bb = bl[lane + 32 * r];
            const u64 bb2 = pk2(bb, bb);
#pragma unroll
            for (int q = 0; q < NPAIR; ++q) {
                accv[q][r] = bb2; acc1[q][r] = 0ull; acc2[q][r] = 0ull;
            }
        }

        for (int c = 0; c < HID / KC; ++c) {
            __syncthreads();
            const float4* __restrict__ src =
                reinterpret_cast<const float4*>(Wl + c * KC * HID);
            float4* dst = reinterpret_cast<float4*>(Wc);
#pragma unroll
            for (int i = 0; i < (KC * HID / 4) / THREADS; ++i)
                dst[tid + i * THREADS] = src[tid + i * THREADS];
            __syncthreads();

#pragma unroll 2
            for (int kk = 0; kk < KC; ++kk) {
                const int k = c * KC + kk;
                u64 w2[8];
#pragma unroll
                for (int r = 0; r < 8; ++r) {
                    const float w = Wc[kk * HID + lane + 32 * r];
                    w2[r] = pk2(w, w);
                }
#pragma unroll
                for (int q = 0; q < NPAIR; ++q) {
                    const u64 av = hv2 [(ps + q) * HID + k];  // LDS.64 broadcast
                    const u64 a1 = hd12[(ps + q) * HID + k];
                    const u64 a2 = hd22[(ps + q) * HID + k];
#pragma unroll
                    for (int r = 0; r < 8; ++r) {
                        fma2(accv[q][r], av, w2[r]);
                        fma2(acc1[q][r], a1, w2[r]);
                        fma2(acc2[q][r], a2, w2[r]);
                    }
                }
            }
        }

        // tanh combine, write next-layer pair state (warp-private, no sync)
#pragma unroll
        for (int r = 0; r < 8; ++r) {
            const int j = lane + 32 * r;
#pragma unroll
            for (int q = 0; q < NPAIR; ++q) {
                float zv[2], z1[2], z2[2];
                upk2(accv[q][r], zv[0], zv[1]);
                upk2(acc1[q][r], z1[0], z1[1]);
                upk2(acc2[q][r], z2[0], z2[1]);
                float a[2], nd1[2], nd2[2];
#pragma unroll
                for (int h = 0; h < 2; ++h) {
                    const float av = tanhf(zv[h]);
                    const float s  = 1.0f - av * av;
                    a[h]   = av;
                    nd1[h] = s * z1[h];
                    nd2[h] = s * (z2[h] - 2.0f * av * z1[h] * z1[h]);
                }
                hv2 [(ps + q) * HID + j] = pk2(a[0],   a[1]);
                hd12[(ps + q) * HID + j] = pk2(nd1[0], nd1[1]);
                hd22[(ps + q) * HID + j] = pk2(nd2[0], nd2[1]);
            }
        }
    }

    // ---- final linear layer: d2u/dx2 = h'' @ W4 (bias drops out) ----
#pragma unroll
    for (int q = 0; q < NPAIR; ++q) {
        float part0 = 0.0f, part1 = 0.0f;
#pragma unroll
        for (int r = 0; r < 8; ++r) {
            const int j = lane + 32 * r;
            const float w = W4[j];
            float h0, h1;
            upk2(hd22[(ps + q) * HID + j], h0, h1);
            part0 = fmaf(h0, w, part0);
            part1 = fmaf(h1, w, part1);
        }
#pragma unroll
        for (int o = 16; o > 0; o >>= 1) {
            part0 += __shfl_xor_sync(0xffffffffu, part0, o);
            part1 += __shfl_xor_sync(0xffffffffu, part1, o);
        }
        if (lane == 0) {
            out[p0 + 2*q + 0] = part0;
            out[p0 + 2*q + 1] = part1;
        }
    }
}

// ---------------------------------------------------------------------------
// Boundary-point kernel: value stream only (small; kept scalar).
// ---------------------------------------------------------------------------
__global__ void __launch_bounds__(THREADS, 2)
pinn_u_kernel(const float* __restrict__ x,
              const float* __restrict__ W0, const float* __restrict__ b0,
              const float* __restrict__ W1, const float* __restrict__ b1,
              const float* __restrict__ W2, const float* __restrict__ b2,
              const float* __restrict__ W3, const float* __restrict__ b3,
              const float* __restrict__ W4, const float* __restrict__ b4,
              float* __restrict__ out)
{
    extern __shared__ float sm[];
    float* hv = sm;                 // [PPB][HID]
    float* Wc = hv + PPB * HID;     // [KC][HID]

    const int tid   = threadIdx.x;
    const int warp  = tid >> 5;
    const int lane  = tid & 31;
    const int p0    = blockIdx.x * PPB + warp * PPW;
    const int wslot = warp * PPW;

    float xs[PPW];
#pragma unroll
    for (int p = 0; p < PPW; ++p) xs[p] = x[p0 + p];

#pragma unroll
    for (int r = 0; r < 8; ++r) {
        const int j = lane + 32 * r;
        const float w  = W0[j];
        const float bb = b0[j];
#pragma unroll
        for (int p = 0; p < PPW; ++p)
            hv[(wslot + p) * HID + j] = tanhf(fmaf(xs[p], w, bb));
    }

    const float* Wls[3] = {W1, W2, W3};
    const float* bls[3] = {b1, b2, b3};

    for (int l = 0; l < 3; ++l) {
        const float* __restrict__ Wl = Wls[l];
        const float* __restrict__ bl = bls[l];

        float accv[PPW][8];
#pragma unroll
        for (int r = 0; r < 8; ++r) {
            const float bb = bl[lane + 32 * r];
#pragma unroll
            for (int p = 0; p < PPW; ++p) accv[p][r] = bb;
        }

        for (int c = 0; c < HID / KC; ++c) {
            __syncthreads();
            const float4* __restrict__ src =
                reinterpret_cast<const float4*>(Wl + c * KC * HID);
            float4* dst = reinterpret_cast<float4*>(Wc);
#pragma unroll
            for (int i = 0; i < (KC * HID / 4) / THREADS; ++i)
                dst[tid + i * THREADS] = src[tid + i * THREADS];
            __syncthreads();

#pragma unroll 2
            for (int kk = 0; kk < KC; ++kk) {
                const int k = c * KC + kk;
                float w[8];
#pragma unroll
                for (int r = 0; r < 8; ++r) w[r] = Wc[kk * HID + lane + 32 * r];
#pragma unroll
                for (int p = 0; p < PPW; ++p) {
                    const float av = hv[(wslot + p) * HID + k];
#pragma unroll
                    for (int r = 0; r < 8; ++r)
                        accv[p][r] = fmaf(av, w[r], accv[p][r]);
                }
            }
        }

#pragma unroll
        for (int r = 0; r < 8; ++r) {
            const int j = lane + 32 * r;
#pragma unroll
            for (int p = 0; p < PPW; ++p)
                hv[(wslot + p) * HID + j] = tanhf(accv[p][r]);
        }
    }

    const float b4v = b4[0];
#pragma unroll
    for (int p = 0; p < PPW; ++p) {
        float part = 0.0f;
#pragma unroll
        for (int r = 0; r < 8; ++r) {
            const int j = lane + 32 * r;
            part = fmaf(hv[(wslot + p) * HID + j], W4[j], part);
        }
#pragma unroll
        for (int o = 16; o > 0; o >>= 1)
            part += __shfl_xor_sync(0xffffffffu, part, o);
        if (lane == 0) out[p0 + p] = part + b4v;
    }
}

// ---------------------------------------------------------------------------
extern "C" void kernel_launch(void* const* d_in, const int* in_sizes, int n_in,
                              void* d_out, int out_size)
{
    const float* x_eq = (const float*)d_in[0];
    const float* x_b  = (const float*)d_in[1];
    const float* W0   = (const float*)d_in[2];
    const float* b0   = (const float*)d_in[3];
    const float* W1   = (const float*)d_in[4];
    const float* b1   = (const float*)d_in[5];
    const float* W2   = (const float*)d_in[6];
    const float* b2   = (const float*)d_in[7];
    const float* W3   = (const float*)d_in[8];
    const float* b3   = (const float*)d_in[9];
    const float* W4   = (const float*)d_in[10];
    const float* b4   = (const float*)d_in[11];
    float* out = (float*)d_out;

    const int n_eq = in_sizes[0];   // 262144
    const int n_b  = in_sizes[1];   // 8192

    const size_t smem_d2 = (size_t)(3 * PPB * HID + KC * HID) * sizeof(float); // 128 KB
    const size_t smem_u  = (size_t)(PPB * HID + KC * HID) * sizeof(float);     // 64 KB

    cudaFuncSetAttribute(pinn_d2_kernel,
                         cudaFuncAttributeMaxDynamicSharedMemorySize, (int)smem_d2);
    cudaFuncSetAttribute(pinn_u_kernel,
                         cudaFuncAttributeMaxDynamicSharedMemorySize, (int)smem_u);

    pinn_d2_kernel<<<n_eq / PPB, THREADS, smem_d2>>>(
        x_eq, W0, b0, W1, b1, W2, b2, W3, b3, W4, out);

    pinn_u_kernel<<<n_b / PPB, THREADS, smem_u>>>(
        x_b, W0, b0, W1, b1, W2, b2, W3, b3, W4, b4, out + n_eq);
}

// round 3
// speedup vs baseline: 1.0992x; 1.0011x over previous
#include <cuda_runtime.h>

#define THREADS 256
#define WARPS   8
#define PPW     4             // points per warp
#define NPAIR   (PPW/2)       // point-pairs per warp
#define PPB     (WARPS*PPW)   // 32 points per block
#define KC      32            // weight rows staged per chunk
#define HID     256

typedef unsigned long long u64;

// ---- packed fp32x2 helpers (Blackwell FFMA2; full fp32 precision) ----
__device__ __forceinline__ u64 pk2(float lo, float hi) {
    u64 r; asm("mov.b64 %0, {%1, %2};" : "=l"(r) : "f"(lo), "f"(hi)); return r;
}
__device__ __forceinline__ void upk2(u64 v, float& lo, float& hi) {
    asm("mov.b64 {%0, %1}, %2;" : "=f"(lo), "=f"(hi) : "l"(v));
}
__device__ __forceinline__ void fma2(u64& d, u64 a, u64 b) {
    asm("fma.rn.f32x2 %0, %1, %2, %0;" : "+l"(d) : "l"(a), "l"(b));
}

// ---------------------------------------------------------------------------
// Equation-point kernel: forward-mode (value, u', u'') with packed f32x2 math.
// Warp owns 4 points = 2 pairs; pair state is u64-interleaved in shared so a
// single LDS.64 broadcast feeds both halves of each FFMA2.
// ---------------------------------------------------------------------------
__global__ void __launch_bounds__(THREADS, 1)
pinn_d2_kernel(const float* __restrict__ x,
               const float* __restrict__ W0, const float* __restrict__ b0,
               const float* __restrict__ W1, const float* __restrict__ b1,
               const float* __restrict__ W2, const float* __restrict__ b2,
               const float* __restrict__ W3, const float* __restrict__ b3,
               const float* __restrict__ W4,
               float* __restrict__ out)
{
    extern __shared__ float sm[];
    u64* hv2  = reinterpret_cast<u64*>(sm);             // [PPB/2][HID] value pairs
    u64* hd12 = hv2  + (PPB/2) * HID;                   // [PPB/2][HID] u' pairs
    u64* hd22 = hd12 + (PPB/2) * HID;                   // [PPB/2][HID] u'' pairs
    float* Wc = reinterpret_cast<float*>(hd22 + (PPB/2) * HID);  // [KC][HID]

    const int tid  = threadIdx.x;
    const int warp = tid >> 5;
    const int lane = tid & 31;
    const int p0   = blockIdx.x * PPB + warp * PPW;     // global point base
    const int ps   = warp * NPAIR;                      // pair-slot base

    // ---- layer 0: scalar input ----
    float xs[PPW];
#pragma unroll
    for (int p = 0; p < PPW; ++p) xs[p] = x[p0 + p];

#pragma unroll
    for (int r = 0; r < 8; ++r) {
        const int j = lane + 32 * r;
        const float w  = W0[j];
        const float bb = b0[j];
#pragma unroll
        for (int q = 0; q < NPAIR; ++q) {
            float a[2], d1[2], d2v[2];
#pragma unroll
            for (int h = 0; h < 2; ++h) {
                const float zv = fmaf(xs[2*q + h], w, bb);
                const float av = tanhf(zv);
                const float s  = 1.0f - av * av;
                a[h]   = av;
                d1[h]  = s * w;
                d2v[h] = s * (-2.0f * av * w * w);
            }
            hv2 [(ps + q) * HID + j] = pk2(a[0],   a[1]);
            hd12[(ps + q) * HID + j] = pk2(d1[0],  d1[1]);
            hd22[(ps + q) * HID + j] = pk2(d2v[0], d2v[1]);
        }
    }

    const float* Wls[3] = {W1, W2, W3};
    const float* bls[3] = {b1, b2, b3};

    for (int l = 0; l < 3; ++l) {
        const float* __restrict__ Wl = Wls[l];
        const float* __restrict__ bl = bls[l];

        u64 accv[NPAIR][8], acc1[NPAIR][8], acc2[NPAIR][8];
#pragma unroll
        for (int r = 0; r < 8; ++r) {
            const float bb = bl[lane + 32 * r];
            const u64 bb2 = pk2(bb, bb);
#pragma unroll
            for (int q = 0; q < NPAIR; ++q) {
                accv[q][r] = bb2; acc1[q][r] = 0ull; acc2[q][r] = 0ull;
            }
        }

        for (int c = 0; c < HID / KC; ++c) {
            __syncthreads();
            const float4* __restrict__ src =
                reinterpret_cast<const float4*>(Wl + c * KC * HID);
            float4* dst = reinterpret_cast<float4*>(Wc);
#pragma unroll
            for (int i = 0; i < (KC * HID / 4) / THREADS; ++i)
                dst[tid + i * THREADS] = src[tid + i * THREADS];
            __syncthreads();

#pragma unroll 2
            for (int kk = 0; kk < KC; ++kk) {
                const int k = c * KC + kk;
                u64 w2[8];
#pragma unroll
                for (int r = 0; r < 8; ++r) {
                    const float w = Wc[kk * HID + lane + 32 * r];
                    w2[r] = pk2(w, w);
                }
#pragma unroll
                for (int q = 0; q < NPAIR; ++q) {
                    const u64 av = hv2 [(ps + q) * HID + k];  // LDS.64 broadcast
                    const u64 a1 = hd12[(ps + q) * HID + k];
                    const u64 a2 = hd22[(ps + q) * HID + k];
#pragma unroll
                    for (int r = 0; r < 8; ++r) {
                        fma2(accv[q][r], av, w2[r]);
                        fma2(acc1[q][r], a1, w2[r]);
                        fma2(acc2[q][r], a2, w2[r]);
                    }
                }
            }
        }

        // tanh combine, write next-layer pair state (warp-private, no sync)
#pragma unroll
        for (int r = 0; r < 8; ++r) {
            const int j = lane + 32 * r;
#pragma unroll
            for (int q = 0; q < NPAIR; ++q) {
                float zv[2], z1[2], z2[2];
                upk2(accv[q][r], zv[0], zv[1]);
                upk2(acc1[q][r], z1[0], z1[1]);
                upk2(acc2[q][r], z2[0], z2[1]);
                float a[2], nd1[2], nd2[2];
#pragma unroll
                for (int h = 0; h < 2; ++h) {
                    const float av = tanhf(zv[h]);
                    const float s  = 1.0f - av * av;
                    a[h]   = av;
                    nd1[h] = s * z1[h];
                    nd2[h] = s * (z2[h] - 2.0f * av * z1[h] * z1[h]);
                }
                hv2 [(ps + q) * HID + j] = pk2(a[0],   a[1]);
                hd12[(ps + q) * HID + j] = pk2(nd1[0], nd1[1]);
                hd22[(ps + q) * HID + j] = pk2(nd2[0], nd2[1]);
            }
        }
    }

    // ---- final linear layer: d2u/dx2 = h'' @ W4 (bias drops out) ----
#pragma unroll
    for (int q = 0; q < NPAIR; ++q) {
        float part0 = 0.0f, part1 = 0.0f;
#pragma unroll
        for (int r = 0; r < 8; ++r) {
            const int j = lane + 32 * r;
            const float w = W4[j];
            float h0, h1;
            upk2(hd22[(ps + q) * HID + j], h0, h1);
            part0 = fmaf(h0, w, part0);
            part1 = fmaf(h1, w, part1);
        }
#pragma unroll
        for (int o = 16; o > 0; o >>= 1) {
            part0 += __shfl_xor_sync(0xffffffffu, part0, o);
            part1 += __shfl_xor_sync(0xffffffffu, part1, o);
        }
        if (lane == 0) {
            out[p0 + 2*q + 0] = part0;
            out[p0 + 2*q + 1] = part1;
        }
    }
}

// ---------------------------------------------------------------------------
// Boundary-point kernel: value stream only (small; kept scalar).
// ---------------------------------------------------------------------------
__global__ void __launch_bounds__(THREADS, 2)
pinn_u_kernel(const float* __restrict__ x,
              const float* __restrict__ W0, const float* __restrict__ b0,
              const float* __restrict__ W1, const float* __restrict__ b1,
              const float* __restrict__ W2, const float* __restrict__ b2,
              const float* __restrict__ W3, const float* __restrict__ b3,
              const float* __restrict__ W4, const float* __restrict__ b4,
              float* __restrict__ out)
{
    extern __shared__ float sm[];
    float* hv = sm;                 // [PPB][HID]
    float* Wc = hv + PPB * HID;     // [KC][HID]

    const int tid   = threadIdx.x;
    const int warp  = tid >> 5;
    const int lane  = tid & 31;
    const int p0    = blockIdx.x * PPB + warp * PPW;
    const int wslot = warp * PPW;

    float xs[PPW];
#pragma unroll
    for (int p = 0; p < PPW; ++p) xs[p] = x[p0 + p];

#pragma unroll
    for (int r = 0; r < 8; ++r) {
        const int j = lane + 32 * r;
        const float w  = W0[j];
        const float bb = b0[j];
#pragma unroll
        for (int p = 0; p < PPW; ++p)
            hv[(wslot + p) * HID + j] = tanhf(fmaf(xs[p], w, bb));
    }

    const float* Wls[3] = {W1, W2, W3};
    const float* bls[3] = {b1, b2, b3};

    for (int l = 0; l < 3; ++l) {
        const float* __restrict__ Wl = Wls[l];
        const float* __restrict__ bl = bls[l];

        float accv[PPW][8];
#pragma unroll
        for (int r = 0; r < 8; ++r) {
            const float bb = bl[lane + 32 * r];
#pragma unroll
            for (int p = 0; p < PPW; ++p) accv[p][r] = bb;
        }

        for (int c = 0; c < HID / KC; ++c) {
            __syncthreads();
            const float4* __restrict__ src =
                reinterpret_cast<const float4*>(Wl + c * KC * HID);
            float4* dst = reinterpret_cast<float4*>(Wc);
#pragma unroll
            for (int i = 0; i < (KC * HID / 4) / THREADS; ++i)
                dst[tid + i * THREADS] = src[tid + i * THREADS];
            __syncthreads();

#pragma unroll 2
            for (int kk = 0; kk < KC; ++kk) {
                const int k = c * KC + kk;
                float w[8];
#pragma unroll
                for (int r = 0; r < 8; ++r) w[r] = Wc[kk * HID + lane + 32 * r];
#pragma unroll
                for (int p = 0; p < PPW; ++p) {
                    const float av = hv[(wslot + p) * HID + k];
#pragma unroll
                    for (int r = 0; r < 8; ++r)
                        accv[p][r] = fmaf(av, w[r], accv[p][r]);
                }
            }
        }

#pragma unroll
        for (int r = 0; r < 8; ++r) {
            const int j = lane + 32 * r;
#pragma unroll
            for (int p = 0; p < PPW; ++p)
                hv[(wslot + p) * HID + j] = tanhf(accv[p][r]);
        }
    }

    const float b4v = b4[0];
#pragma unroll
    for (int p = 0; p < PPW; ++p) {
        float part = 0.0f;
#pragma unroll
        for (int r = 0; r < 8; ++r) {
            const int j = lane + 32 * r;
            part = fmaf(hv[(wslot + p) * HID + j], W4[j], part);
        }
#pragma unroll
        for (int o = 16; o > 0; o >>= 1)
            part += __shfl_xor_sync(0xffffffffu, part, o);
        if (lane == 0) out[p0 + p] = part + b4v;
    }
}

// ---------------------------------------------------------------------------
extern "C" void kernel_launch(void* const* d_in, const int* in_sizes, int n_in,
                              void* d_out, int out_size)
{
    const float* x_eq = (const float*)d_in[0];
    const float* x_b  = (const float*)d_in[1];
    const float* W0   = (const float*)d_in[2];
    const float* b0   = (const float*)d_in[3];
    const float* W1   = (const float*)d_in[4];
    const float* b1   = (const float*)d_in[5];
    const float* W2   = (const float*)d_in[6];
    const float* b2   = (const float*)d_in[7];
    const float* W3   = (const float*)d_in[8];
    const float* b3   = (const float*)d_in[9];
    const float* W4   = (const float*)d_in[10];
    const float* b4   = (const float*)d_in[11];
    float* out = (float*)d_out;

    const int n_eq = in_sizes[0];   // 262144
    const int n_b  = in_sizes[1];   // 8192

    const size_t smem_d2 = (size_t)(3 * PPB * HID + KC * HID) * sizeof(float); // 128 KB
    const size_t smem_u  = (size_t)(PPB * HID + KC * HID) * sizeof(float);     // 64 KB

    cudaFuncSetAttribute(pinn_d2_kernel,
                         cudaFuncAttributeMaxDynamicSharedMemorySize, (int)smem_d2);
    cudaFuncSetAttribute(pinn_u_kernel,
                         cudaFuncAttributeMaxDynamicSharedMemorySize, (int)smem_u);

    pinn_d2_kernel<<<n_eq / PPB, THREADS, smem_d2>>>(
        x_eq, W0, b0, W1, b1, W2, b2, W3, b3, W4, out);

    pinn_u_kernel<<<n_b / PPB, THREADS, smem_u>>>(
        x_b, W0, b0, W1, b1, W2, b2, W3, b3, W4, b4, out + n_eq);
}

// round 4
// speedup vs baseline: 1.0993x; 1.0001x over previous
#include <cuda_runtime.h>

#define THREADS 256
#define WARPS   8
#define PPW     4             // points per warp
#define NPAIR   (PPW/2)       // point-pairs per warp
#define PPB     (WARPS*PPW)   // 32 points per block
#define KC      32            // weight rows staged per chunk
#define HID     256

typedef unsigned long long u64;

// ---- packed fp32x2 helpers (Blackwell FFMA2; full fp32 precision) ----
__device__ __forceinline__ u64 pk2(float lo, float hi) {
    u64 r; asm("mov.b64 %0, {%1, %2};" : "=l"(r) : "f"(lo), "f"(hi)); return r;
}
__device__ __forceinline__ void upk2(u64 v, float& lo, float& hi) {
    asm("mov.b64 {%0, %1}, %2;" : "=f"(lo), "=f"(hi) : "l"(v));
}
__device__ __forceinline__ void fma2(u64& d, u64 a, u64 b) {
    asm("fma.rn.f32x2 %0, %1, %2, %0;" : "+l"(d) : "l"(a), "l"(b));
}

// ---------------------------------------------------------------------------
// Equation-point kernel: forward-mode (value, u', u'') with packed f32x2 math.
// Warp owns 4 points = 2 pairs; pair state is u64-interleaved in shared so a
// single LDS.64 broadcast feeds both halves of each FFMA2.
// ---------------------------------------------------------------------------
__global__ void __launch_bounds__(THREADS, 1)
pinn_d2_kernel(const float* __restrict__ x,
               const float* __restrict__ W0, const float* __restrict__ b0,
               const float* __restrict__ W1, const float* __restrict__ b1,
               const float* __restrict__ W2, const float* __restrict__ b2,
               const float* __restrict__ W3, const float* __restrict__ b3,
               const float* __restrict__ W4,
               float* __restrict__ out)
{
    extern __shared__ float sm[];
    u64* hv2  = reinterpret_cast<u64*>(sm);             // [PPB/2][HID] value pairs
    u64* hd12 = hv2  + (PPB/2) * HID;                   // [PPB/2][HID] u' pairs
    u64* hd22 = hd12 + (PPB/2) * HID;                   // [PPB/2][HID] u'' pairs
    float* Wc = reinterpret_cast<float*>(hd22 + (PPB/2) * HID);  // [KC][HID]

    const int tid  = threadIdx.x;
    const int warp = tid >> 5;
    const int lane = tid & 31;
    const int p0   = blockIdx.x * PPB + warp * PPW;     // global point base
    const int ps   = warp * NPAIR;                      // pair-slot base

    // ---- layer 0: scalar input ----
    float xs[PPW];
#pragma unroll
    for (int p = 0; p < PPW; ++p) xs[p] = x[p0 + p];

#pragma unroll
    for (int r = 0; r < 8; ++r) {
        const int j = lane + 32 * r;
        const float w  = W0[j];
        const float bb = b0[j];
#pragma unroll
        for (int q = 0; q < NPAIR; ++q) {
            float a[2], d1[2], d2v[2];
#pragma unroll
            for (int h = 0; h < 2; ++h) {
                const float zv = fmaf(xs[2*q + h], w, bb);
                const float av = tanhf(zv);
                const float s  = 1.0f - av * av;
                a[h]   = av;
                d1[h]  = s * w;
                d2v[h] = s * (-2.0f * av * w * w);
            }
            hv2 [(ps + q) * HID + j] = pk2(a[0],   a[1]);
            hd12[(ps + q) * HID + j] = pk2(d1[0],  d1[1]);
            hd22[(ps + q) * HID + j] = pk2(d2v[0], d2v[1]);
        }
    }

    const float* Wls[3] = {W1, W2, W3};
    const float* bls[3] = {b1, b2, b3};

    for (int l = 0; l < 3; ++l) {
        const float* __restrict__ Wl = Wls[l];
        const float* __restrict__ bl = bls[l];

        u64 accv[NPAIR][8], acc1[NPAIR][8], acc2[NPAIR][8];
#pragma unroll
        for (int r = 0; r < 8; ++r) {
            const float bb = bl[lane + 32 * r];
            const u64 bb2 = pk2(bb, bb);
#pragma unroll
            for (int q = 0; q < NPAIR; ++q) {
                accv[q][r] = bb2; acc1[q][r] = 0ull; acc2[q][r] = 0ull;
            }
        }

        for (int c = 0; c < HID / KC; ++c) {
            __syncthreads();
            const float4* __restrict__ src =
                reinterpret_cast<const float4*>(Wl + c * KC * HID);
            float4* dst = reinterpret_cast<float4*>(Wc);
#pragma unroll
            for (int i = 0; i < (KC * HID / 4) / THREADS; ++i)
                dst[tid + i * THREADS] = src[tid + i * THREADS];
            __syncthreads();

#pragma unroll 2
            for (int kk = 0; kk < KC; ++kk) {
                const int k = c * KC + kk;
                u64 w2[8];
#pragma unroll
                for (int r = 0; r < 8; ++r) {
                    const float w = Wc[kk * HID + lane + 32 * r];
                    w2[r] = pk2(w, w);
                }
#pragma unroll
                for (int q = 0; q < NPAIR; ++q) {
                    const u64 av = hv2 [(ps + q) * HID + k];  // LDS.64 broadcast
                    const u64 a1 = hd12[(ps + q) * HID + k];
                    const u64 a2 = hd22[(ps + q) * HID + k];
#pragma unroll
                    for (int r = 0; r < 8; ++r) {
                        fma2(accv[q][r], av, w2[r]);
                        fma2(acc1[q][r], a1, w2[r]);
                        fma2(acc2[q][r], a2, w2[r]);
                    }
                }
            }
        }

        // tanh combine, write next-layer pair state (warp-private, no sync)
#pragma unroll
        for (int r = 0; r < 8; ++r) {
            const int j = lane + 32 * r;
#pragma unroll
            for (int q = 0; q < NPAIR; ++q) {
                float zv[2], z1[2], z2[2];
                upk2(accv[q][r], zv[0], zv[1]);
                upk2(acc1[q][r], z1[0], z1[1]);
                upk2(acc2[q][r], z2[0], z2[1]);
                float a[2], nd1[2], nd2[2];
#pragma unroll
                for (int h = 0; h < 2; ++h) {
                    const float av = tanhf(zv[h]);
                    const float s  = 1.0f - av * av;
                    a[h]   = av;
                    nd1[h] = s * z1[h];
                    nd2[h] = s * (z2[h] - 2.0f * av * z1[h] * z1[h]);
                }
                hv2 [(ps + q) * HID + j] = pk2(a[0],   a[1]);
                hd12[(ps + q) * HID + j] = pk2(nd1[0], nd1[1]);
                hd22[(ps + q) * HID + j] = pk2(nd2[0], nd2[1]);
            }
        }
    }

    // ---- final linear layer: d2u/dx2 = h'' @ W4 (bias drops out) ----
#pragma unroll
    for (int q = 0; q < NPAIR; ++q) {
        float part0 = 0.0f, part1 = 0.0f;
#pragma unroll
        for (int r = 0; r < 8; ++r) {
            const int j = lane + 32 * r;
            const float w = W4[j];
            float h0, h1;
            upk2(hd22[(ps + q) * HID + j], h0, h1);
            part0 = fmaf(h0, w, part0);
            part1 = fmaf(h1, w, part1);
        }
#pragma unroll
        for (int o = 16; o > 0; o >>= 1) {
            part0 += __shfl_xor_sync(0xffffffffu, part0, o);
            part1 += __shfl_xor_sync(0xffffffffu, part1, o);
        }
        if (lane == 0) {
            out[p0 + 2*q + 0] = part0;
            out[p0 + 2*q + 1] = part1;
        }
    }
}

// ---------------------------------------------------------------------------
// Boundary-point kernel: value stream only (small; kept scalar).
// ---------------------------------------------------------------------------
__global__ void __launch_bounds__(THREADS, 2)
pinn_u_kernel(const float* __restrict__ x,
              const float* __restrict__ W0, const float* __restrict__ b0,
              const float* __restrict__ W1, const float* __restrict__ b1,
              const float* __restrict__ W2, const float* __restrict__ b2,
              const float* __restrict__ W3, const float* __restrict__ b3,
              const float* __restrict__ W4, const float* __restrict__ b4,
              float* __restrict__ out)
{
    extern __shared__ float sm[];
    float* hv = sm;                 // [PPB][HID]
    float* Wc = hv + PPB * HID;     // [KC][HID]

    const int tid   = threadIdx.x;
    const int warp  = tid >> 5;
    const int lane  = tid & 31;
    const int p0    = blockIdx.x * PPB + warp * PPW;
    const int wslot = warp * PPW;

    float xs[PPW];
#pragma unroll
    for (int p = 0; p < PPW; ++p) xs[p] = x[p0 + p];

#pragma unroll
    for (int r = 0; r < 8; ++r) {
        const int j = lane + 32 * r;
        const float w  = W0[j];
        const float bb = b0[j];
#pragma unroll
        for (int p = 0; p < PPW; ++p)
            hv[(wslot + p) * HID + j] = tanhf(fmaf(xs[p], w, bb));
    }

    const float* Wls[3] = {W1, W2, W3};
    const float* bls[3] = {b1, b2, b3};

    for (int l = 0; l < 3; ++l) {
        const float* __restrict__ Wl = Wls[l];
        const float* __restrict__ bl = bls[l];

        float accv[PPW][8];
#pragma unroll
        for (int r = 0; r < 8; ++r) {
            const float bb = bl[lane + 32 * r];
#pragma unroll
            for (int p = 0; p < PPW; ++p) accv[p][r] = bb;
        }

        for (int c = 0; c < HID / KC; ++c) {
            __syncthreads();
            const float4* __restrict__ src =
                reinterpret_cast<const float4*>(Wl + c * KC * HID);
            float4* dst = reinterpret_cast<float4*>(Wc);
#pragma unroll
            for (int i = 0; i < (KC * HID / 4) / THREADS; ++i)
                dst[tid + i * THREADS] = src[tid + i * THREADS];
            __syncthreads();

#pragma unroll 2
            for (int kk = 0; kk < KC; ++kk) {
                const int k = c * KC + kk;
                float w[8];
#pragma unroll
                for (int r = 0; r < 8; ++r) w[r] = Wc[kk * HID + lane + 32 * r];
#pragma unroll
                for (int p = 0; p < PPW; ++p) {
                    const float av = hv[(wslot + p) * HID + k];
#pragma unroll
                    for (int r = 0; r < 8; ++r)
                        accv[p][r] = fmaf(av, w[r], accv[p][r]);
                }
            }
        }

#pragma unroll
        for (int r = 0; r < 8; ++r) {
            const int j = lane + 32 * r;
#pragma unroll
            for (int p = 0; p < PPW; ++p)
                hv[(wslot + p) * HID + j] = tanhf(accv[p][r]);
        }
    }

    const float b4v = b4[0];
#pragma unroll
    for (int p = 0; p < PPW; ++p) {
        float part = 0.0f;
#pragma unroll
        for (int r = 0; r < 8; ++r) {
            const int j = lane + 32 * r;
            part = fmaf(hv[(wslot + p) * HID + j], W4[j], part);
        }
#pragma unroll
        for (int o = 16; o > 0; o >>= 1)
            part += __shfl_xor_sync(0xffffffffu, part, o);
        if (lane == 0) out[p0 + p] = part + b4v;
    }
}

// ---------------------------------------------------------------------------
extern "C" void kernel_launch(void* const* d_in, const int* in_sizes, int n_in,
                              void* d_out, int out_size)
{
    const float* x_eq = (const float*)d_in[0];
    const float* x_b  = (const float*)d_in[1];
    const float* W0   = (const float*)d_in[2];
    const float* b0   = (const float*)d_in[3];
    const float* W1   = (const float*)d_in[4];
    const float* b1   = (const float*)d_in[5];
    const float* W2   = (const float*)d_in[6];
    const float* b2   = (const float*)d_in[7];
    const float* W3   = (const float*)d_in[8];
    const float* b3   = (const float*)d_in[9];
    const float* W4   = (const float*)d_in[10];
    const float* b4   = (const float*)d_in[11];
    float* out = (float*)d_out;

    const int n_eq = in_sizes[0];   // 262144
    const int n_b  = in_sizes[1];   // 8192

    const size_t smem_d2 = (size_t)(3 * PPB * HID + KC * HID) * sizeof(float); // 128 KB
    const size_t smem_u  = (size_t)(PPB * HID + KC * HID) * sizeof(float);     // 64 KB

    cudaFuncSetAttribute(pinn_d2_kernel,
                         cudaFuncAttributeMaxDynamicSharedMemorySize, (int)smem_d2);
    cudaFuncSetAttribute(pinn_u_kernel,
                         cudaFuncAttributeMaxDynamicSharedMemorySize, (int)smem_u);

    pinn_d2_kernel<<<n_eq / PPB, THREADS, smem_d2>>>(
        x_eq, W0, b0, W1, b1, W2, b2, W3, b3, W4, out);

    pinn_u_kernel<<<n_b / PPB, THREADS, smem_u>>>(
        x_b, W0, b0, W1, b1, W2, b2, W3, b3, W4, b4, out + n_eq);
}

// round 5
// speedup vs baseline: 1.0996x; 1.0003x over previous
#include <cuda_runtime.h>

#define THREADS 256
#define WARPS   8
#define PPW     4             // points per warp
#define NPAIR   (PPW/2)       // point-pairs per warp
#define PPB     (WARPS*PPW)   // 32 points per block
#define KC      32            // weight rows staged per chunk
#define HID     256

typedef unsigned long long u64;

// ---- packed fp32x2 helpers (Blackwell FFMA2; full fp32 precision) ----
__device__ __forceinline__ u64 pk2(float lo, float hi) {
    u64 r; asm("mov.b64 %0, {%1, %2};" : "=l"(r) : "f"(lo), "f"(hi)); return r;
}
__device__ __forceinline__ void upk2(u64 v, float& lo, float& hi) {
    asm("mov.b64 {%0, %1}, %2;" : "=f"(lo), "=f"(hi) : "l"(v));
}
__device__ __forceinline__ void fma2(u64& d, u64 a, u64 b) {
    asm("fma.rn.f32x2 %0, %1, %2, %0;" : "+l"(d) : "l"(a), "l"(b));
}

// ---------------------------------------------------------------------------
// Equation-point kernel: forward-mode (value, u', u'') with packed f32x2 math.
// Warp owns 4 points = 2 pairs; pair state is u64-interleaved in shared so a
// single LDS.64 broadcast feeds both halves of each FFMA2.
// ---------------------------------------------------------------------------
__global__ void __launch_bounds__(THREADS, 1)
pinn_d2_kernel(const float* __restrict__ x,
               const float* __restrict__ W0, const float* __restrict__ b0,
               const float* __restrict__ W1, const float* __restrict__ b1,
               const float* __restrict__ W2, const float* __restrict__ b2,
               const float* __restrict__ W3, const float* __restrict__ b3,
               const float* __restrict__ W4,
               float* __restrict__ out)
{
    extern __shared__ float sm[];
    u64* hv2  = reinterpret_cast<u64*>(sm);             // [PPB/2][HID] value pairs
    u64* hd12 = hv2  + (PPB/2) * HID;                   // [PPB/2][HID] u' pairs
    u64* hd22 = hd12 + (PPB/2) * HID;                   // [PPB/2][HID] u'' pairs
    float* Wc = reinterpret_cast<float*>(hd22 + (PPB/2) * HID);  // [KC][HID]

    const int tid  = threadIdx.x;
    const int warp = tid >> 5;
    const int lane = tid & 31;
    const int p0   = blockIdx.x * PPB + warp * PPW;     // global point base
    const int ps   = warp * NPAIR;                      // pair-slot base

    // ---- layer 0: scalar input ----
    float xs[PPW];
#pragma unroll
    for (int p = 0; p < PPW; ++p) xs[p] = x[p0 + p];

#pragma unroll
    for (int r = 0; r < 8; ++r) {
        const int j = lane + 32 * r;
        const float w  = W0[j];
        const float bb = b0[j];
#pragma unroll
        for (int q = 0; q < NPAIR; ++q) {
            float a[2], d1[2], d2v[2];
#pragma unroll
            for (int h = 0; h < 2; ++h) {
                const float zv = fmaf(xs[2*q + h], w, bb);
                const float av = tanhf(zv);
                const float s  = 1.0f - av * av;
                a[h]   = av;
                d1[h]  = s * w;
                d2v[h] = s * (-2.0f * av * w * w);
            }
            hv2 [(ps + q) * HID + j] = pk2(a[0],   a[1]);
            hd12[(ps + q) * HID + j] = pk2(d1[0],  d1[1]);
            hd22[(ps + q) * HID + j] = pk2(d2v[0], d2v[1]);
        }
    }

    const float* Wls[3] = {W1, W2, W3};
    const float* bls[3] = {b1, b2, b3};

    for (int l = 0; l < 3; ++l) {
        const float* __restrict__ Wl = Wls[l];
        const float* __restrict__ bl = bls[l];

        u64 accv[NPAIR][8], acc1[NPAIR][8], acc2[NPAIR][8];
#pragma unroll
        for (int r = 0; r < 8; ++r) {
            const float bb = bl[lane + 32 * r];
            const u64 bb2 = pk2(bb, bb);
#pragma unroll
            for (int q = 0; q < NPAIR; ++q) {
                accv[q][r] = bb2; acc1[q][r] = 0ull; acc2[q][r] = 0ull;
            }
        }

        for (int c = 0; c < HID / KC; ++c) {
            __syncthreads();
            const float4* __restrict__ src =
                reinterpret_cast<const float4*>(Wl + c * KC * HID);
            float4* dst = reinterpret_cast<float4*>(Wc);
#pragma unroll
            for (int i = 0; i < (KC * HID / 4) / THREADS; ++i)
                dst[tid + i * THREADS] = src[tid + i * THREADS];
            __syncthreads();

#pragma unroll 2
            for (int kk = 0; kk < KC; ++kk) {
                const int k = c * KC + kk;
                u64 w2[8];
#pragma unroll
                for (int r = 0; r < 8; ++r) {
                    const float w = Wc[kk * HID + lane + 32 * r];
                    w2[r] = pk2(w, w);
                }
#pragma unroll
                for (int q = 0; q < NPAIR; ++q) {
                    const u64 av = hv2 [(ps + q) * HID + k];  // LDS.64 broadcast
                    const u64 a1 = hd12[(ps + q) * HID + k];
                    const u64 a2 = hd22[(ps + q) * HID + k];
#pragma unroll
                    for (int r = 0; r < 8; ++r) {
                        fma2(accv[q][r], av, w2[r]);
                        fma2(acc1[q][r], a1, w2[r]);
                        fma2(acc2[q][r], a2, w2[r]);
                    }
                }
            }
        }

        // tanh combine, write next-layer pair state (warp-private, no sync)
#pragma unroll
        for (int r = 0; r < 8; ++r) {
            const int j = lane + 32 * r;
#pragma unroll
            for (int q = 0; q < NPAIR; ++q) {
                float zv[2], z1[2], z2[2];
                upk2(accv[q][r], zv[0], zv[1]);
                upk2(acc1[q][r], z1[0], z1[1]);
                upk2(acc2[q][r], z2[0], z2[1]);
                float a[2], nd1[2], nd2[2];
#pragma unroll
                for (int h = 0; h < 2; ++h) {
                    const float av = tanhf(zv[h]);
                    const float s  = 1.0f - av * av;
                    a[h]   = av;
                    nd1[h] = s * z1[h];
                    nd2[h] = s * (z2[h] - 2.0f * av * z1[h] * z1[h]);
                }
                hv2 [(ps + q) * HID + j] = pk2(a[0],   a[1]);
                hd12[(ps + q) * HID + j] = pk2(nd1[0], nd1[1]);
                hd22[(ps + q) * HID + j] = pk2(nd2[0], nd2[1]);
            }
        }
    }

    // ---- final linear layer: d2u/dx2 = h'' @ W4 (bias drops out) ----
#pragma unroll
    for (int q = 0; q < NPAIR; ++q) {
        float part0 = 0.0f, part1 = 0.0f;
#pragma unroll
        for (int r = 0; r < 8; ++r) {
            const int j = lane + 32 * r;
            const float w = W4[j];
            float h0, h1;
            upk2(hd22[(ps + q) * HID + j], h0, h1);
            part0 = fmaf(h0, w, part0);
            part1 = fmaf(h1, w, part1);
        }
#pragma unroll
        for (int o = 16; o > 0; o >>= 1) {
            part0 += __shfl_xor_sync(0xffffffffu, part0, o);
            part1 += __shfl_xor_sync(0xffffffffu, part1, o);
        }
        if (lane == 0) {
            out[p0 + 2*q + 0] = part0;
            out[p0 + 2*q + 1] = part1;
        }
    }
}

// ---------------------------------------------------------------------------
// Boundary-point kernel: value stream only (small; kept scalar).
// ---------------------------------------------------------------------------
__global__ void __launch_bounds__(THREADS, 2)
pinn_u_kernel(const float* __restrict__ x,
              const float* __restrict__ W0, const float* __restrict__ b0,
              const float* __restrict__ W1, const float* __restrict__ b1,
              const float* __restrict__ W2, const float* __restrict__ b2,
              const float* __restrict__ W3, const float* __restrict__ b3,
              const float* __restrict__ W4, const float* __restrict__ b4,
              float* __restrict__ out)
{
    extern __shared__ float sm[];
    float* hv = sm;                 // [PPB][HID]
    float* Wc = hv + PPB * HID;     // [KC][HID]

    const int tid   = threadIdx.x;
    const int warp  = tid >> 5;
    const int lane  = tid & 31;
    const int p0    = blockIdx.x * PPB + warp * PPW;
    const int wslot = warp * PPW;

    float xs[PPW];
#pragma unroll
    for (int p = 0; p < PPW; ++p) xs[p] = x[p0 + p];

#pragma unroll
    for (int r = 0; r < 8; ++r) {
        const int j = lane + 32 * r;
        const float w  = W0[j];
        const float bb = b0[j];
#pragma unroll
        for (int p = 0; p < PPW; ++p)
            hv[(wslot + p) * HID + j] = tanhf(fmaf(xs[p], w, bb));
    }

    const float* Wls[3] = {W1, W2, W3};
    const float* bls[3] = {b1, b2, b3};

    for (int l = 0; l < 3; ++l) {
        const float* __restrict__ Wl = Wls[l];
        const float* __restrict__ bl = bls[l];

        float accv[PPW][8];
#pragma unroll
        for (int r = 0; r < 8; ++r) {
            const float bb = bl[lane + 32 * r];
#pragma unroll
            for (int p = 0; p < PPW; ++p) accv[p][r] = bb;
        }

        for (int c = 0; c < HID / KC; ++c) {
            __syncthreads();
            const float4* __restrict__ src =
                reinterpret_cast<const float4*>(Wl + c * KC * HID);
            float4* dst = reinterpret_cast<float4*>(Wc);
#pragma unroll
            for (int i = 0; i < (KC * HID / 4) / THREADS; ++i)
                dst[tid + i * THREADS] = src[tid + i * THREADS];
            __syncthreads();

#pragma unroll 2
            for (int kk = 0; kk < KC; ++kk) {
                const int k = c * KC + kk;
                float w[8];
#pragma unroll
                for (int r = 0; r < 8; ++r) w[r] = Wc[kk * HID + lane + 32 * r];
#pragma unroll
                for (int p = 0; p < PPW; ++p) {
                    const float av = hv[(wslot + p) * HID + k];
#pragma unroll
                    for (int r = 0; r < 8; ++r)
                        accv[p][r] = fmaf(av, w[r], accv[p][r]);
                }
            }
        }

#pragma unroll
        for (int r = 0; r < 8; ++r) {
            const int j = lane + 32 * r;
#pragma unroll
            for (int p = 0; p < PPW; ++p)
                hv[(wslot + p) * HID + j] = tanhf(accv[p][r]);
        }
    }

    const float b4v = b4[0];
#pragma unroll
    for (int p = 0; p < PPW; ++p) {
        float part = 0.0f;
#pragma unroll
        for (int r = 0; r < 8; ++r) {
            const int j = lane + 32 * r;
            part = fmaf(hv[(wslot + p) * HID + j], W4[j], part);
        }
#pragma unroll
        for (int o = 16; o > 0; o >>= 1)
            part += __shfl_xor_sync(0xffffffffu, part, o);
        if (lane == 0) out[p0 + p] = part + b4v;
    }
}

// ---------------------------------------------------------------------------
extern "C" void kernel_launch(void* const* d_in, const int* in_sizes, int n_in,
                              void* d_out, int out_size)
{
    const float* x_eq = (const float*)d_in[0];
    const float* x_b  = (const float*)d_in[1];
    const float* W0   = (const float*)d_in[2];
    const float* b0   = (const float*)d_in[3];
    const float* W1   = (const float*)d_in[4];
    const float* b1   = (const float*)d_in[5];
    const float* W2   = (const float*)d_in[6];
    const float* b2   = (const float*)d_in[7];
    const float* W3   = (const float*)d_in[8];
    const float* b3   = (const float*)d_in[9];
    const float* W4   = (const float*)d_in[10];
    const float* b4   = (const float*)d_in[11];
    float* out = (float*)d_out;

    const int n_eq = in_sizes[0];   // 262144
    const int n_b  = in_sizes[1];   // 8192

    const size_t smem_d2 = (size_t)(3 * PPB * HID + KC * HID) * sizeof(float); // 128 KB
    const size_t smem_u  = (size_t)(PPB * HID + KC * HID) * sizeof(float);     // 64 KB

    cudaFuncSetAttribute(pinn_d2_kernel,
                         cudaFuncAttributeMaxDynamicSharedMemorySize, (int)smem_d2);
    cudaFuncSetAttribute(pinn_u_kernel,
                         cudaFuncAttributeMaxDynamicSharedMemorySize, (int)smem_u);

    pinn_d2_kernel<<<n_eq / PPB, THREADS, smem_d2>>>(
        x_eq, W0, b0, W1, b1, W2, b2, W3, b3, W4, out);

    pinn_u_kernel<<<n_b / PPB, THREADS, smem_u>>>(
        x_b, W0, b0, W1, b1, W2, b2, W3, b3, W4, b4, out + n_eq);
}

// round 7
// speedup vs baseline: 1.6798x; 1.5277x over previous
#include <cuda_runtime.h>
#include <cuda_bf16.h>
#include <cstdint>

#define HID  256
#define NPTS 270336               // 262144 eq + 8192 boundary

// ---------------------------------------------------------------------------
// Static device scratch
// state[gen][stream v/d1/d2][hi=0,lo=1][pt][k]
__device__ __nv_bfloat16 g_state[2][3][2][NPTS][HID];
// transposed split weights: wt[layer][img][j][k] = split(W[k][j])
__device__ __nv_bfloat16 g_wt[3][2][HID][HID];
// z' f32 scratch (written stream-1 epilogue, read stream-2 epilogue, L2-hot)
__device__ float g_z1[(size_t)NPTS * HID];

// ---------------------------------------------------------------------------
#define SWZ128(o) ((uint32_t)(o) ^ ((((uint32_t)(o)) >> 3) & 0x70))

__device__ __forceinline__ uint32_t smem_u32(const void* p) {
    uint32_t a;
    asm("{ .reg .u64 t; cvta.to.shared.u64 t, %1; cvt.u32.u64 %0, t; }"
        : "=r"(a) : "l"(p));
    return a;
}
__device__ __forceinline__ void ldsm4(uint32_t* r, uint32_t a) {
    asm volatile("ldmatrix.sync.aligned.m8n8.x4.shared.b16 {%0,%1,%2,%3}, [%4];"
                 : "=r"(r[0]), "=r"(r[1]), "=r"(r[2]), "=r"(r[3]) : "r"(a));
}
__device__ __forceinline__ void mma_bf16(float* c, const uint32_t* a,
                                         uint32_t b0, uint32_t b1) {
    asm volatile(
        "mma.sync.aligned.m16n8k16.row.col.f32.bf16.bf16.f32 "
        "{%0,%1,%2,%3}, {%4,%5,%6,%7}, {%8,%9}, {%0,%1,%2,%3};"
        : "+f"(c[0]), "+f"(c[1]), "+f"(c[2]), "+f"(c[3])
        : "r"(a[0]), "r"(a[1]), "r"(a[2]), "r"(a[3]), "r"(b0), "r"(b1));
}
__device__ __forceinline__ void split_bf(float v, __nv_bfloat16& hi, __nv_bfloat16& lo) {
    hi = __float2bfloat16_rn(v);
    lo = __float2bfloat16_rn(v - __bfloat162float(hi));
}
__device__ __forceinline__ uint32_t pack_bf(__nv_bfloat16 a, __nv_bfloat16 b) {
    return (uint32_t)__bfloat16_as_ushort(a) | ((uint32_t)__bfloat16_as_ushort(b) << 16);
}
__device__ __forceinline__ float bf_lo(uint32_t u) {
    return __bfloat162float(__ushort_as_bfloat16((unsigned short)(u & 0xFFFF)));
}
__device__ __forceinline__ float bf_hi(uint32_t u) {
    return __bfloat162float(__ushort_as_bfloat16((unsigned short)(u >> 16)));
}

// ---------------------------------------------------------------------------
__global__ void prep_kernel(const float* __restrict__ W1,
                            const float* __restrict__ W2,
                            const float* __restrict__ W3) {
    const float* Ws[3] = {W1, W2, W3};
    int idx = blockIdx.x * 256 + threadIdx.x;   // < 196608
    int l = idx >> 16, r = idx & 0xFFFF;
    int j = r >> 8, k = r & 255;
    __nv_bfloat16 hi, lo;
    split_bf(Ws[l][k * HID + j], hi, lo);
    g_wt[l][0][j][k] = hi;
    g_wt[l][1][j][k] = lo;
}

__global__ void layer0_kernel(const float* __restrict__ xe,
                              const float* __restrict__ xb,
                              const float* __restrict__ W0,
                              const float* __restrict__ b0, int n_eq) {
    int tid = threadIdx.x, wid = tid >> 5, lane = tid & 31;
    int pt = blockIdx.x * 8 + wid;
    bool eq = pt < n_eq;
    float xv = eq ? xe[pt] : xb[pt - n_eq];
    int j0 = lane * 8;
    __nv_bfloat16 vh[8], vl[8], ah[8], al[8], bh[8], bl[8];
#pragma unroll
    for (int i = 0; i < 8; ++i) {
        float w = W0[j0 + i];
        float z = fmaf(xv, w, b0[j0 + i]);
        float a = tanhf(z);
        float sf = 1.0f - a * a;
        float d1 = eq ? sf * w : 0.0f;
        float d2 = eq ? (-2.0f * a * sf * w * w) : 0.0f;
        split_bf(a,  vh[i], vl[i]);
        split_bf(d1, ah[i], al[i]);
        split_bf(d2, bh[i], bl[i]);
    }
    size_t off = (size_t)pt * HID + j0;
    *(uint4*)(&g_state[0][0][0][0][0] + off) = *(uint4*)vh;
    *(uint4*)(&g_state[0][0][1][0][0] + off) = *(uint4*)vl;
    *(uint4*)(&g_state[0][1][0][0][0] + off) = *(uint4*)ah;
    *(uint4*)(&g_state[0][1][1][0][0] + off) = *(uint4*)al;
    *(uint4*)(&g_state[0][2][0][0][0] + off) = *(uint4*)bh;
    *(uint4*)(&g_state[0][2][1][0][0] + off) = *(uint4*)bl;
}

// ---------------------------------------------------------------------------
// hidden layer: 3 sequential stream GEMMs on mma.sync + tanh-combine epilogue
// ---------------------------------------------------------------------------
#define SM_A    0                 // 2 imgs x [128][64] bf16 = 32 KB
#define SM_B    32768             // 2 imgs x [256][64] bf16 = 64 KB
#define SM_BIAS 98304             // 256 f32
#define SMEM_HK 99328

__global__ void __launch_bounds__(256, 1)
hidden_kernel(int gin, int gout, int lw, const float* __restrict__ bias)
{
    extern __shared__ char sm[];
    const uint32_t sb = smem_u32(sm);
    float* bs = (float*)(sm + SM_BIAS);
    const int tid = threadIdx.x, lane = tid & 31, wid = tid >> 5;
    const int wm = wid >> 2, wn = wid & 3;        // warp grid 2(m) x 4(n)
    const int pt0 = blockIdx.x * 128;

    bs[tid] = bias[tid];

    const __nv_bfloat16* wbase = &g_wt[lw][0][0][0];
    __nv_bfloat16* pv_h = &g_state[gout][0][0][0][0];
    __nv_bfloat16* pv_l = &g_state[gout][0][1][0][0];
    __nv_bfloat16* p1_h = &g_state[gout][1][0][0][0];
    __nv_bfloat16* p1_l = &g_state[gout][1][1][0][0];
    __nv_bfloat16* p2_h = &g_state[gout][2][0][0][0];
    __nv_bfloat16* p2_l = &g_state[gout][2][1][0][0];

    for (int s = 0; s < 3; ++s) {
        float acc[4][8][4];
#pragma unroll
        for (int mi = 0; mi < 4; ++mi)
#pragma unroll
            for (int nj = 0; nj < 8; ++nj)
#pragma unroll
                for (int q = 0; q < 4; ++q) acc[mi][nj][q] = 0.0f;

        const __nv_bfloat16* abase = &g_state[gin][s][0][0][0];   // img stride NPTS*HID

        for (int c = 0; c < 4; ++c) {
            __syncthreads();
            // stage A: 2 imgs x 1024 16B-units, SW128
#pragma unroll
            for (int i = 0; i < 8; ++i) {
                int idx = tid + i * 256;
                int img = idx >> 10, u = idx & 1023, pt = u >> 3, k8 = u & 7;
                uint4 v = *(const uint4*)(abase + (size_t)img * NPTS * HID
                                          + (size_t)(pt0 + pt) * HID + c * 64 + k8 * 8);
                *(uint4*)(sm + SM_A + img * 16384 + SWZ128(pt * 128 + k8 * 16)) = v;
            }
            // stage B: 2 imgs x 2048 16B-units, SW128
#pragma unroll
            for (int i = 0; i < 16; ++i) {
                int idx = tid + i * 256;
                int img = idx >> 11, u = idx & 2047, n = u >> 3, k8 = u & 7;
                uint4 v = *(const uint4*)(wbase + (size_t)img * HID * HID
                                          + n * HID + c * 64 + k8 * 8);
                *(uint4*)(sm + SM_B + img * 32768 + SWZ128(n * 128 + k8 * 16)) = v;
            }
            __syncthreads();

            const int rA = wm * 64 + (lane & 15);
            const int rB = wn * 64 + (lane & 15);
#pragma unroll
            for (int kk = 0; kk < 4; ++kk) {
                const uint32_t kb = kk * 32 + ((lane >> 4) << 4);
                uint32_t ah[4][4], al[4][4], bh[4][4], bl2[4][4];
#pragma unroll
                for (int mi = 0; mi < 4; ++mi) {
                    uint32_t off = SWZ128((uint32_t)((rA + mi * 16) * 128) + kb);
                    ldsm4(ah[mi], sb + SM_A + off);
                    ldsm4(al[mi], sb + SM_A + 16384 + off);
                }
#pragma unroll
                for (int g = 0; g < 4; ++g) {
                    uint32_t off = SWZ128((uint32_t)((rB + g * 16) * 128) + kb);
                    ldsm4(bh[g],  sb + SM_B + off);
                    ldsm4(bl2[g], sb + SM_B + 32768 + off);
                }
#pragma unroll
                for (int mi = 0; mi < 4; ++mi)
#pragma unroll
                    for (int g = 0; g < 4; ++g) {
                        mma_bf16(acc[mi][2*g],   ah[mi], bh[g][0],  bh[g][2]);
                        mma_bf16(acc[mi][2*g+1], ah[mi], bh[g][1],  bh[g][3]);
                        mma_bf16(acc[mi][2*g],   ah[mi], bl2[g][0], bl2[g][2]);
                        mma_bf16(acc[mi][2*g+1], ah[mi], bl2[g][1], bl2[g][3]);
                        mma_bf16(acc[mi][2*g],   al[mi], bh[g][0],  bh[g][2]);
                        mma_bf16(acc[mi][2*g+1], al[mi], bh[g][1],  bh[g][3]);
                    }
            }
        }

        // ---- epilogue: c frag (row lane>>2 +{0,8}; cols (lane&3)*2 +{0,1}) ----
        const int mr  = pt0 + wm * 64 + (lane >> 2);
        const int nc0 = wn * 64 + (lane & 3) * 2;
#pragma unroll
        for (int mi = 0; mi < 4; ++mi)
#pragma unroll
            for (int nj = 0; nj < 8; ++nj) {
                const int n = nc0 + nj * 8;
#pragma unroll
                for (int h = 0; h < 2; ++h) {
                    const int m = mr + mi * 16 + h * 8;
                    const size_t o = (size_t)m * HID + n;
                    const float f0 = acc[mi][nj][2*h], f1 = acc[mi][nj][2*h+1];
                    if (s == 0) {
                        float a0 = tanhf(f0 + bs[n]);
                        float a1 = tanhf(f1 + bs[n + 1]);
                        __nv_bfloat16 h0, l0, h1, l1;
                        split_bf(a0, h0, l0); split_bf(a1, h1, l1);
                        *(uint32_t*)(pv_h + o) = pack_bf(h0, h1);
                        *(uint32_t*)(pv_l + o) = pack_bf(l0, l1);
                    } else {
                        const uint32_t uh = *(const uint32_t*)(pv_h + o);
                        const uint32_t ul = *(const uint32_t*)(pv_l + o);
                        const float a0 = bf_lo(uh) + bf_lo(ul);
                        const float a1 = bf_hi(uh) + bf_hi(ul);
                        const float s0 = 1.0f - a0 * a0;
                        const float s1 = 1.0f - a1 * a1;
                        __nv_bfloat16 h0, l0, h1, l1;
                        if (s == 1) {
                            *(float2*)(g_z1 + o) = make_float2(f0, f1);
                            split_bf(s0 * f0, h0, l0);
                            split_bf(s1 * f1, h1, l1);
                            *(uint32_t*)(p1_h + o) = pack_bf(h0, h1);
                            *(uint32_t*)(p1_l + o) = pack_bf(l0, l1);
                        } else {
                            const float2 z1 = *(const float2*)(g_z1 + o);
                            split_bf(s0 * (f0 - 2.0f * a0 * z1.x * z1.x), h0, l0);
                            split_bf(s1 * (f1 - 2.0f * a1 * z1.y * z1.y), h1, l1);
                            *(uint32_t*)(p2_h + o) = pack_bf(h0, h1);
                            *(uint32_t*)(p2_l + o) = pack_bf(l0, l1);
                        }
                    }
                }
            }
    }
}

// ---------------------------------------------------------------------------
__global__ void final_kernel(const float* __restrict__ W4,
                             const float* __restrict__ b4,
                             float* __restrict__ out, int n_eq, int gfin) {
    int tid = threadIdx.x, wid = tid >> 5, lane = tid & 31;
    int pt = blockIdx.x * 8 + wid;
    bool eq = pt < n_eq;
    int s = eq ? 2 : 0;
    int j0 = lane * 8;
    const __nv_bfloat16* ph = &g_state[gfin][s][0][0][0] + (size_t)pt * HID + j0;
    const __nv_bfloat16* pl = &g_state[gfin][s][1][0][0] + (size_t)pt * HID + j0;
    uint4 uh = *(const uint4*)ph, ul = *(const uint4*)pl;
    const __nv_bfloat16* hh = (const __nv_bfloat16*)&uh;
    const __nv_bfloat16* ll = (const __nv_bfloat16*)&ul;
    float sum = 0.0f;
#pragma unroll
    for (int i = 0; i < 8; ++i)
        sum = fmaf(__bfloat162float(hh[i]) + __bfloat162float(ll[i]), W4[j0 + i], sum);
#pragma unroll
    for (int o = 16; o > 0; o >>= 1)
        sum += __shfl_xor_sync(0xffffffffu, sum, o);
    if (lane == 0) out[pt] = sum + (eq ? 0.0f : b4[0]);
}

// ---------------------------------------------------------------------------
extern "C" void kernel_launch(void* const* d_in, const int* in_sizes, int n_in,
                              void* d_out, int out_size)
{
    const float* x_eq = (const float*)d_in[0];
    const float* x_b  = (const float*)d_in[1];
    const float* W0 = (const float*)d_in[2];  const float* b0 = (const float*)d_in[3];
    const float* W1 = (const float*)d_in[4];  const float* b1 = (const float*)d_in[5];
    const float* W2 = (const float*)d_in[6];  const float* b2 = (const float*)d_in[7];
    const float* W3 = (const float*)d_in[8];  const float* b3 = (const float*)d_in[9];
    const float* W4 = (const float*)d_in[10]; const float* b4 = (const float*)d_in[11];
    float* out = (float*)d_out;

    const int n_eq = in_sizes[0];
    const int n_b  = in_sizes[1];
    const int npts = n_eq + n_b;

    cudaFuncSetAttribute(hidden_kernel,
                         cudaFuncAttributeMaxDynamicSharedMemorySize, SMEM_HK);

    prep_kernel<<<3 * HID * HID / 256, 256>>>(W1, W2, W3);
    layer0_kernel<<<npts / 8, 256>>>(x_eq, x_b, W0, b0, n_eq);
    hidden_kernel<<<npts / 128, 256, SMEM_HK>>>(0, 1, 0, b1);
    hidden_kernel<<<npts / 128, 256, SMEM_HK>>>(1, 0, 1, b2);
    hidden_kernel<<<npts / 128, 256, SMEM_HK>>>(0, 1, 2, b3);
    final_kernel<<<npts / 8, 256>>>(W4, b4, out, n_eq, 1);
}

// round 8
// speedup vs baseline: 1.8855x; 1.1224x over previous
#include <cuda_runtime.h>
#include <cuda_fp16.h>
#include <cstdint>

#define HID  256
#define NPTS 270336               // 262144 eq + 8192 boundary

// ---------------------------------------------------------------------------
// Static device scratch
// state[gen][stream v/d1/d2][hi=0,lo=1][pt][k]
__device__ __half g_state[2][3][2][NPTS][HID];
// transposed split weights: wt[layer][img][j][k] = split(W[k][j])
__device__ __half g_wt[3][2][HID][HID];
// z' f32 scratch (written stream-1 epilogue, read stream-2 epilogue by same thread)
__device__ float g_z1[(size_t)NPTS * HID];

// ---------------------------------------------------------------------------
#define SWZ128(o) ((uint32_t)(o) ^ ((((uint32_t)(o)) >> 3) & 0x70))

__device__ __forceinline__ uint32_t smem_u32(const void* p) {
    uint32_t a;
    asm("{ .reg .u64 t; cvta.to.shared.u64 t, %1; cvt.u32.u64 %0, t; }"
        : "=r"(a) : "l"(p));
    return a;
}
__device__ __forceinline__ void ldsm4(uint32_t* r, uint32_t a) {
    asm volatile("ldmatrix.sync.aligned.m8n8.x4.shared.b16 {%0,%1,%2,%3}, [%4];"
                 : "=r"(r[0]), "=r"(r[1]), "=r"(r[2]), "=r"(r[3]) : "r"(a));
}
__device__ __forceinline__ void mma_f16(float* c, const uint32_t* a,
                                        uint32_t b0, uint32_t b1) {
    asm volatile(
        "mma.sync.aligned.m16n8k16.row.col.f32.f16.f16.f32 "
        "{%0,%1,%2,%3}, {%4,%5,%6,%7}, {%8,%9}, {%0,%1,%2,%3};"
        : "+f"(c[0]), "+f"(c[1]), "+f"(c[2]), "+f"(c[3])
        : "r"(a[0]), "r"(a[1]), "r"(a[2]), "r"(a[3]), "r"(b0), "r"(b1));
}
#define CP16(dst, src) \
    asm volatile("cp.async.cg.shared.global [%0], [%1], 16;" \
                 :: "r"(dst), "l"(src) : "memory")
#define CP_COMMIT() asm volatile("cp.async.commit_group;" ::: "memory")
#define CP_WAIT1()  asm volatile("cp.async.wait_group 1;" ::: "memory")
#define CP_WAIT0()  asm volatile("cp.async.wait_group 0;" ::: "memory")

__device__ __forceinline__ void split_h(float v, __half& hi, __half& lo) {
    hi = __float2half_rn(v);
    lo = __float2half_rn(v - __half2float(hi));
}
__device__ __forceinline__ uint32_t pack_h(__half a, __half b) {
    return (uint32_t)__half_as_ushort(a) | ((uint32_t)__half_as_ushort(b) << 16);
}
__device__ __forceinline__ float h_lo(uint32_t u) {
    return __half2float(__ushort_as_half((unsigned short)(u & 0xFFFF)));
}
__device__ __forceinline__ float h_hi(uint32_t u) {
    return __half2float(__ushort_as_half((unsigned short)(u >> 16)));
}

// ---------------------------------------------------------------------------
__global__ void prep_kernel(const float* __restrict__ W1,
                            const float* __restrict__ W2,
                            const float* __restrict__ W3) {
    const float* Ws[3] = {W1, W2, W3};
    int idx = blockIdx.x * 256 + threadIdx.x;   // < 196608
    int l = idx >> 16, r = idx & 0xFFFF;
    int j = r >> 8, k = r & 255;
    __half hi, lo;
    split_h(Ws[l][k * HID + j], hi, lo);
    g_wt[l][0][j][k] = hi;
    g_wt[l][1][j][k] = lo;
}

__global__ void layer0_kernel(const float* __restrict__ xe,
                              const float* __restrict__ xb,
                              const float* __restrict__ W0,
                              const float* __restrict__ b0, int n_eq) {
    int tid = threadIdx.x, wid = tid >> 5, lane = tid & 31;
    int pt = blockIdx.x * 8 + wid;
    bool eq = pt < n_eq;
    float xv = eq ? xe[pt] : xb[pt - n_eq];
    int j0 = lane * 8;
    __half vh[8], vl[8], ah[8], al[8], bh[8], bl[8];
#pragma unroll
    for (int i = 0; i < 8; ++i) {
        float w = W0[j0 + i];
        float z = fmaf(xv, w, b0[j0 + i]);
        float a = tanhf(z);
        float sf = 1.0f - a * a;
        float d1 = eq ? sf * w : 0.0f;
        float d2 = eq ? (-2.0f * a * sf * w * w) : 0.0f;
        split_h(a,  vh[i], vl[i]);
        split_h(d1, ah[i], al[i]);
        split_h(d2, bh[i], bl[i]);
    }
    size_t off = (size_t)pt * HID + j0;
    *(uint4*)(&g_state[0][0][0][0][0] + off) = *(uint4*)vh;
    *(uint4*)(&g_state[0][0][1][0][0] + off) = *(uint4*)vl;
    *(uint4*)(&g_state[0][1][0][0][0] + off) = *(uint4*)ah;
    *(uint4*)(&g_state[0][1][1][0][0] + off) = *(uint4*)al;
    *(uint4*)(&g_state[0][2][0][0][0] + off) = *(uint4*)bh;
    *(uint4*)(&g_state[0][2][1][0][0] + off) = *(uint4*)bl;
}

// ---------------------------------------------------------------------------
// hidden layer: fused (stream, k-chunk) loop, cp.async double-buffered staging
// ---------------------------------------------------------------------------
#define BUF_STRIDE 98304          // A 32KB + B 64KB per buffer
#define SM_Aoff(b) ((b) * BUF_STRIDE)
#define SM_Boff(b) ((b) * BUF_STRIDE + 32768)
#define SM_BIAS    196608
#define SMEM_HK    197632

__global__ void __launch_bounds__(256, 1)
hidden_kernel(int gin, int gout, int lw, const float* __restrict__ bias)
{
    extern __shared__ char sm[];
    const uint32_t sb = smem_u32(sm);
    float* bs = (float*)(sm + SM_BIAS);
    const int tid = threadIdx.x, lane = tid & 31, wid = tid >> 5;
    const int wm = wid >> 2, wn = wid & 3;        // warp grid 2(m) x 4(n)
    const int pt0 = blockIdx.x * 128;

    bs[tid] = bias[tid];

    const __half* wbase = &g_wt[lw][0][0][0];
    const __half* sbase = &g_state[gin][0][0][0][0];   // stream stride 2*NPTS*HID
    __half* pv_h = &g_state[gout][0][0][0][0];
    __half* pv_l = &g_state[gout][0][1][0][0];
    __half* p1_h = &g_state[gout][1][0][0][0];
    __half* p1_l = &g_state[gout][1][1][0][0];
    __half* p2_h = &g_state[gout][2][0][0][0];
    __half* p2_l = &g_state[gout][2][1][0][0];

    // ---- async stage of iteration it = s*4 + c into buffer it&1 ----
    auto stage = [&](int it) {
        const int s = it >> 2, c = it & 3;
        const int buf = it & 1;
        const __half* ab = sbase + (size_t)s * 2 * NPTS * HID;
#pragma unroll
        for (int i = 0; i < 8; ++i) {              // A: 2048 x 16B
            int idx = tid + i * 256;
            int img = idx >> 10, u = idx & 1023, pt = u >> 3, k8 = u & 7;
            const void* src = ab + (size_t)img * NPTS * HID
                              + (size_t)(pt0 + pt) * HID + c * 64 + k8 * 8;
            CP16(sb + SM_Aoff(buf) + img * 16384 + SWZ128(pt * 128 + k8 * 16), src);
        }
#pragma unroll
        for (int i = 0; i < 16; ++i) {             // B: 4096 x 16B
            int idx = tid + i * 256;
            int img = idx >> 11, u = idx & 2047, n = u >> 3, k8 = u & 7;
            const void* src = wbase + (size_t)img * HID * HID + n * HID + c * 64 + k8 * 8;
            CP16(sb + SM_Boff(buf) + img * 32768 + SWZ128(n * 128 + k8 * 16), src);
        }
        CP_COMMIT();
    };

    float acc[4][8][4];
    stage(0);

    for (int it = 0; it < 12; ++it) {
        const int s = it >> 2, c = it & 3;
        const int buf = it & 1;

        if (c == 0) {
#pragma unroll
            for (int mi = 0; mi < 4; ++mi)
#pragma unroll
                for (int nj = 0; nj < 8; ++nj)
#pragma unroll
                    for (int q = 0; q < 4; ++q) acc[mi][nj][q] = 0.0f;
        }

        if (it + 1 < 12) { stage(it + 1); CP_WAIT1(); }
        else             { CP_WAIT0(); }
        __syncthreads();

        // ---- compute chunk (same fragment mapping as R7, verified) ----
        const int rA = wm * 64 + (lane & 15);
        const int rB = wn * 64 + (lane & 15);
#pragma unroll
        for (int kk = 0; kk < 4; ++kk) {
            const uint32_t kb = kk * 32 + ((lane >> 4) << 4);
            uint32_t ah[4][4], al[4][4], bh[4][4], bl2[4][4];
#pragma unroll
            for (int mi = 0; mi < 4; ++mi) {
                uint32_t off = SWZ128((uint32_t)((rA + mi * 16) * 128) + kb);
                ldsm4(ah[mi], sb + SM_Aoff(buf) + off);
                ldsm4(al[mi], sb + SM_Aoff(buf) + 16384 + off);
            }
#pragma unroll
            for (int g = 0; g < 4; ++g) {
                uint32_t off = SWZ128((uint32_t)((rB + g * 16) * 128) + kb);
                ldsm4(bh[g],  sb + SM_Boff(buf) + off);
                ldsm4(bl2[g], sb + SM_Boff(buf) + 32768 + off);
            }
#pragma unroll
            for (int mi = 0; mi < 4; ++mi)
#pragma unroll
                for (int g = 0; g < 4; ++g) {
                    mma_f16(acc[mi][2*g],   ah[mi], bh[g][0],  bh[g][2]);
                    mma_f16(acc[mi][2*g+1], ah[mi], bh[g][1],  bh[g][3]);
                    mma_f16(acc[mi][2*g],   ah[mi], bl2[g][0], bl2[g][2]);
                    mma_f16(acc[mi][2*g+1], ah[mi], bl2[g][1], bl2[g][3]);
                    mma_f16(acc[mi][2*g],   al[mi], bh[g][0],  bh[g][2]);
                    mma_f16(acc[mi][2*g+1], al[mi], bh[g][1],  bh[g][3]);
                }
        }
        __syncthreads();   // compute done before this buffer is re-staged next iter

        if (c == 3) {
            // ---- epilogue: c frag rows lane>>2 +{0,8}; cols (lane&3)*2 +{0,1} ----
            const int mr  = pt0 + wm * 64 + (lane >> 2);
            const int nc0 = wn * 64 + (lane & 3) * 2;
#pragma unroll
            for (int mi = 0; mi < 4; ++mi)
#pragma unroll
                for (int nj = 0; nj < 8; ++nj) {
                    const int n = nc0 + nj * 8;
#pragma unroll
                    for (int h = 0; h < 2; ++h) {
                        const int m = mr + mi * 16 + h * 8;
                        const size_t o = (size_t)m * HID + n;
                        const float f0 = acc[mi][nj][2*h], f1 = acc[mi][nj][2*h+1];
                        __half h0, l0, h1, l1;
                        if (s == 0) {
                            float a0 = tanhf(f0 + bs[n]);
                            float a1 = tanhf(f1 + bs[n + 1]);
                            split_h(a0, h0, l0); split_h(a1, h1, l1);
                            *(uint32_t*)(pv_h + o) = pack_h(h0, h1);
                            *(uint32_t*)(pv_l + o) = pack_h(l0, l1);
                        } else {
                            const uint32_t uh = *(const uint32_t*)(pv_h + o);
                            const uint32_t ul = *(const uint32_t*)(pv_l + o);
                            const float a0 = h_lo(uh) + h_lo(ul);
                            const float a1 = h_hi(uh) + h_hi(ul);
                            const float s0 = 1.0f - a0 * a0;
                            const float s1 = 1.0f - a1 * a1;
                            if (s == 1) {
                                *(float2*)(g_z1 + o) = make_float2(f0, f1);
                                split_h(s0 * f0, h0, l0);
                                split_h(s1 * f1, h1, l1);
                                *(uint32_t*)(p1_h + o) = pack_h(h0, h1);
                                *(uint32_t*)(p1_l + o) = pack_h(l0, l1);
                            } else {
                                const float2 z1 = *(const float2*)(g_z1 + o);
                                split_h(s0 * (f0 - 2.0f * a0 * z1.x * z1.x), h0, l0);
                                split_h(s1 * (f1 - 2.0f * a1 * z1.y * z1.y), h1, l1);
                                *(uint32_t*)(p2_h + o) = pack_h(h0, h1);
                                *(uint32_t*)(p2_l + o) = pack_h(l0, l1);
                            }
                        }
                    }
                }
        }
    }
}

// ---------------------------------------------------------------------------
__global__ void final_kernel(const float* __restrict__ W4,
                             const float* __restrict__ b4,
                             float* __restrict__ out, int n_eq, int gfin) {
    int tid = threadIdx.x, wid = tid >> 5, lane = tid & 31;
    int pt = blockIdx.x * 8 + wid;
    bool eq = pt < n_eq;
    int s = eq ? 2 : 0;
    int j0 = lane * 8;
    const __half* ph = &g_state[gfin][s][0][0][0] + (size_t)pt * HID + j0;
    const __half* pl = &g_state[gfin][s][1][0][0] + (size_t)pt * HID + j0;
    uint4 uh = *(const uint4*)ph, ul = *(const uint4*)pl;
    const __half* hh = (const __half*)&uh;
    const __half* ll = (const __half*)&ul;
    float sum = 0.0f;
#pragma unroll
    for (int i = 0; i < 8; ++i)
        sum = fmaf(__half2float(hh[i]) + __half2float(ll[i]), W4[j0 + i], sum);
#pragma unroll
    for (int o = 16; o > 0; o >>= 1)
        sum += __shfl_xor_sync(0xffffffffu, sum, o);
    if (lane == 0) out[pt] = sum + (eq ? 0.0f : b4[0]);
}

// ---------------------------------------------------------------------------
extern "C" void kernel_launch(void* const* d_in, const int* in_sizes, int n_in,
                              void* d_out, int out_size)
{
    const float* x_eq = (const float*)d_in[0];
    const float* x_b  = (const float*)d_in[1];
    const float* W0 = (const float*)d_in[2];  const float* b0 = (const float*)d_in[3];
    const float* W1 = (const float*)d_in[4];  const float* b1 = (const float*)d_in[5];
    const float* W2 = (const float*)d_in[6];  const float* b2 = (const float*)d_in[7];
    const float* W3 = (const float*)d_in[8];  const float* b3 = (const float*)d_in[9];
    const float* W4 = (const float*)d_in[10]; const float* b4 = (const float*)d_in[11];
    float* out = (float*)d_out;

    const int n_eq = in_sizes[0];
    const int n_b  = in_sizes[1];
    const int npts = n_eq + n_b;

    cudaFuncSetAttribute(hidden_kernel,
                         cudaFuncAttributeMaxDynamicSharedMemorySize, SMEM_HK);

    prep_kernel<<<3 * HID * HID / 256, 256>>>(W1, W2, W3);
    layer0_kernel<<<npts / 8, 256>>>(x_eq, x_b, W0, b0, n_eq);
    hidden_kernel<<<npts / 128, 256, SMEM_HK>>>(0, 1, 0, b1);
    hidden_kernel<<<npts / 128, 256, SMEM_HK>>>(1, 0, 1, b2);
    hidden_kernel<<<npts / 128, 256, SMEM_HK>>>(0, 1, 2, b3);
    final_kernel<<<npts / 8, 256>>>(W4, b4, out, n_eq, 1);
}